// round 12
// baseline (speedup 1.0000x reference)
#include <cuda_runtime.h>
#include <cuda_bf16.h>
#include <cstdint>

#define BATCH 2048
#define CAND  16
#define DIM   256
#define ADJW  96                    // 2*3*16
#define OUTW  (DIM + ADJW + 1)      // 353
#define THRED 0.8f

// ---- fused kernel geometry (R8 base: best known 25.6us) ----
#define NB     7                    // batches per block
#define SLOTS  (NB + 6)             // 13 batch tiles incl. +-3 halo
#define BPAD   264                  // bf16 row stride (132 words == 4 mod 32: ldsm clean)
#define FTHR   448                  // threads (14 warps)
#define NROWST (SLOTS * CAND)       // 208 tile rows

#define OFF_TILES  0
#define SZ_TILES   (NROWST * BPAD * 2)                  // 109824 B
#define OFF_RSUM   (OFF_TILES + SZ_TILES)
#define SZ_RSUM    (NB * 6 * CAND * 4)                  // 2688 B
#define OFF_INVS   (OFF_RSUM + SZ_RSUM)
#define SZ_INVS    (NB * CAND * 4)                      // 448 B
#define OFF_INVN   (OFF_INVS + SZ_INVS)
#define SZ_INVN    (NROWST * 4)                         // 832 B
#define OFF_NMV    (OFF_INVN + SZ_INVN)
#define SZ_NMV     (NROWST * 4)                         // 832 B
#define SMEM_TOTAL (OFF_NMV + SZ_NMV)                   // 114624 B -> 2 CTAs/SM

#define FGRID ((BATCH + NB - 1) / NB)                   // 293 blocks ~ one wave

__device__ __forceinline__ uint32_t smem_u32(const void* p) {
    uint32_t a;
    asm("{ .reg .u64 t; cvta.to.shared.u64 t, %1; cvt.u32.u64 %0, t; }"
        : "=r"(a) : "l"(p));
    return a;
}

__device__ __forceinline__ void ldsm4(uint32_t addr, uint32_t& r0, uint32_t& r1,
                                      uint32_t& r2, uint32_t& r3) {
    asm volatile("ldmatrix.sync.aligned.m8n8.x4.shared.b16 {%0,%1,%2,%3}, [%4];"
                 : "=r"(r0), "=r"(r1), "=r"(r2), "=r"(r3) : "r"(addr));
}

__device__ __forceinline__ void mma16816(float* c, uint32_t a0, uint32_t a1,
                                         uint32_t a2, uint32_t a3,
                                         uint32_t b0, uint32_t b1) {
    asm volatile(
        "mma.sync.aligned.m16n8k16.row.col.f32.bf16.bf16.f32 "
        "{%0,%1,%2,%3}, {%4,%5,%6,%7}, {%8,%9}, {%0,%1,%2,%3};\n"
        : "+f"(c[0]), "+f"(c[1]), "+f"(c[2]), "+f"(c[3])
        : "r"(a0), "r"(a1), "r"(a2), "r"(a3), "r"(b0), "r"(b1));
}

// ---------------------------------------------------------------------------
// K_all: everything in one kernel.
//  cols [256,353): band cosine adjacency (R8 structure: bf16 tiles, ldmatrix,
//                  self-product MMA norms, threshold/gate/L1-normalize)
//  cols [0,256):   neighbor-mean, fp32 from emb (L2-hot re-read), rolling
//                  13-slot window per (cand, dim-chunk) pair.
// ---------------------------------------------------------------------------
__global__ __launch_bounds__(FTHR, 2) void k_all(const float* __restrict__ emb,
                                                 const int* __restrict__ nm,
                                                 float* __restrict__ out) {
    extern __shared__ __align__(16) char smraw[];
    __nv_bfloat16* tiles = reinterpret_cast<__nv_bfloat16*>(smraw + OFF_TILES); // [208][264]
    float* rsum = reinterpret_cast<float*>(smraw + OFF_RSUM);                   // [NB][6][16]
    float* invs = reinterpret_cast<float*>(smraw + OFF_INVS);                   // [NB][16]
    float* invn = reinterpret_cast<float*>(smraw + OFF_INVN);                   // [208]
    float* nmv  = reinterpret_cast<float*>(smraw + OFF_NMV);                    // [208]

    const int b0   = blockIdx.x * NB;
    const int t    = threadIdx.x;
    const int wid  = t >> 5;
    const int lane = t & 31;

    // ---- streaming copy+cast: 208 rows ----
    const int l8 = lane * 8;
    for (int r = wid; r < NROWST; r += FTHR / 32) {
        const int bb = b0 - 3 + (r >> 4);
        float4 v0 = make_float4(0.f, 0.f, 0.f, 0.f);
        float4 v1 = v0;
        if ((unsigned)bb < BATCH) {
            const float4* src = reinterpret_cast<const float4*>(
                emb + ((size_t)bb * CAND + (r & 15)) * DIM);
            v0 = src[lane * 2];
            v1 = src[lane * 2 + 1];
        }
        __nv_bfloat162 o[4];
        o[0] = __floats2bfloat162_rn(v0.x, v0.y);
        o[1] = __floats2bfloat162_rn(v0.z, v0.w);
        o[2] = __floats2bfloat162_rn(v1.x, v1.y);
        o[3] = __floats2bfloat162_rn(v1.z, v1.w);
        *reinterpret_cast<uint4*>(&tiles[(size_t)r * BPAD + l8]) = *reinterpret_cast<uint4*>(o);
    }

    // ---- mask cache: nmv[slot][j] (OOB batches -> 0) ----
    if (t < NROWST) {
        const int bb = b0 - 3 + (t >> 4);
        nmv[t] = ((unsigned)bb < BATCH) ? (float)nm[bb * CAND + (t & 15)] : 0.f;
    }
    __syncthreads();

    const int g  = lane >> 2;           // 0..7
    const int tg = lane & 3;            // 0..3
    const int jb = tg * 2;
    const int lmoff = (lane & 15) * BPAD + (lane >> 4) * 8;   // elements
    const uint32_t tiles_base = smem_u32(tiles);

    // ---- self-product MMAs: warps 0..12 compute invn for tile wid ----
    if (wid < SLOTS) {
        uint32_t sad = tiles_base + (uint32_t)(wid * CAND * BPAD + lmoff) * 2;
        float s0[4] = {0.f, 0.f, 0.f, 0.f};
        float s1[4] = {0.f, 0.f, 0.f, 0.f};
        #pragma unroll
        for (int kt = 0; kt < 16; kt++) {
            uint32_t a0, a1, a2, a3;
            ldsm4(sad, a0, a1, a2, a3);
            sad += 32;
            mma16816(s0, a0, a1, a2, a3, a0, a2);
            mma16816(s1, a0, a1, a2, a3, a1, a3);
        }
        if (tg == (g >> 1)) {
            invn[wid * CAND + g]     = rsqrtf(fmaxf((g & 1) ? s0[1] : s0[0], 1e-12f));
            invn[wid * CAND + g + 8] = rsqrtf(fmaxf((g & 1) ? s1[3] : s1[2], 1e-12f));
        }
    }

    // ---- pair MMAs: warp wid -> bi = wid/2, cps {0,1,2} or {3,4,5} ----
    const int bi = wid >> 1;            // 0..6
    const int cpb = (wid & 1) * 3;      // 0 (left) or 3 (right)
    const int slot = bi + 3;            // center tile slot

    uint32_t aad = tiles_base + (uint32_t)(slot * CAND * BPAD + lmoff) * 2;
    int bslot[3];
    uint32_t bad[3];
    #pragma unroll
    for (int e = 0; e < 3; e++) {
        bslot[e] = (cpb == 0) ? (slot - 1 - e) : (slot + 1 + e);
        bad[e] = tiles_base + (uint32_t)(bslot[e] * CAND * BPAD + lmoff) * 2;
    }

    float acc[3][8];
    #pragma unroll
    for (int e = 0; e < 3; e++)
        #pragma unroll
        for (int x = 0; x < 8; x++) acc[e][x] = 0.f;

    #pragma unroll
    for (int kt = 0; kt < 16; kt++) {
        uint32_t a0, a1, a2, a3;
        ldsm4(aad, a0, a1, a2, a3);
        aad += 32;
        #pragma unroll
        for (int e = 0; e < 3; e++) {
            uint32_t m0, m1, m2, m3;
            ldsm4(bad[e], m0, m1, m2, m3);
            bad[e] += 32;
            mma16816(acc[e],     a0, a1, a2, a3, m0, m2);
            mma16816(acc[e] + 4, a0, a1, a2, a3, m1, m3);
        }
    }
    __syncthreads();   // invn complete block-wide

    // ---- gates from mask cache ----
    float gj[4][3];
    const int js[4] = {jb, jb + 1, jb + 8, jb + 9};
    #pragma unroll
    for (int jx = 0; jx < 4; jx++) {
        float a, b, c;
        if (cpb == 0) {         // left: masks of batches b-1, b-2, b-3
            a = nmv[(slot - 1) * CAND + js[jx]];
            b = nmv[(slot - 2) * CAND + js[jx]];
            c = nmv[(slot - 3) * CAND + js[jx]];
        } else {                // right: masks of batches b, b+1, b+2
            a = nmv[slot * CAND + js[jx]];
            b = nmv[(slot + 1) * CAND + js[jx]];
            c = nmv[(slot + 2) * CAND + js[jx]];
        }
        gj[jx][0] = a;
        gj[jx][1] = a * b;
        gj[jx][2] = a * b * c;
    }

    // ---- epilogue: cosine scale, threshold, gate, partial row sums ----
    const float inA0 = invn[slot * CAND + g];
    const float inA8 = invn[slot * CAND + g + 8];
    #pragma unroll
    for (int e = 0; e < 3; e++) {
        const int cp = cpb + e;
        const float* np = &invn[bslot[e] * CAND];
        const float ib0 = np[jb], ib1 = np[jb + 1], ib8 = np[jb + 8], ib9 = np[jb + 9];
        auto thr = [](float v, float ge) {
            v = (v > THRED) ? fminf(v, 1.f) : 0.f;
            return v * ge;
        };
        acc[e][0] = thr(acc[e][0] * inA0 * ib0, gj[0][e]);
        acc[e][1] = thr(acc[e][1] * inA0 * ib1, gj[1][e]);
        acc[e][2] = thr(acc[e][2] * inA8 * ib0, gj[0][e]);
        acc[e][3] = thr(acc[e][3] * inA8 * ib1, gj[1][e]);
        acc[e][4] = thr(acc[e][4] * inA0 * ib8, gj[2][e]);
        acc[e][5] = thr(acc[e][5] * inA0 * ib9, gj[3][e]);
        acc[e][6] = thr(acc[e][6] * inA8 * ib8, gj[2][e]);
        acc[e][7] = thr(acc[e][7] * inA8 * ib9, gj[3][e]);

        float sA = acc[e][0] + acc[e][1] + acc[e][4] + acc[e][5]; // row g
        float sB = acc[e][2] + acc[e][3] + acc[e][6] + acc[e][7]; // row g+8
        sA += __shfl_xor_sync(0xffffffffu, sA, 1);
        sA += __shfl_xor_sync(0xffffffffu, sA, 2);
        sB += __shfl_xor_sync(0xffffffffu, sB, 1);
        sB += __shfl_xor_sync(0xffffffffu, sB, 2);
        if (tg == 0) {
            rsum[(bi * 6 + cp) * CAND + g]     = sA;
            rsum[(bi * 6 + cp) * CAND + g + 8] = sB;
        }
    }
    __syncthreads();

    // ---- invs: per output row 1 / (L1 sum + ones col) ----
    if (t < NB * CAND) {
        const int tb = t >> 4, i = t & 15;
        float s = 1.0f;
        #pragma unroll
        for (int cp = 0; cp < 6; cp++) s += rsum[(tb * 6 + cp) * CAND + i];
        invs[t] = 1.0f / fmaxf(s, 1e-12f);
    }
    __syncthreads();

    // ---- normalized adjacency writes (guard partial last block) ----
    if (b0 + bi < BATCH) {
        const float ivA = invs[bi * CAND + g];
        const float ivB = invs[bi * CAND + g + 8];
        #pragma unroll
        for (int e = 0; e < 3; e++) {
            const int cp = cpb + e;
            float* oA = out + (size_t)((b0 + bi) * CAND + g)     * OUTW + DIM + cp * CAND + jb;
            float* oB = out + (size_t)((b0 + bi) * CAND + g + 8) * OUTW + DIM + cp * CAND + jb;
            oA[0] = acc[e][0] * ivA;  oA[1] = acc[e][1] * ivA;
            oA[8] = acc[e][4] * ivA;  oA[9] = acc[e][5] * ivA;
            oB[0] = acc[e][2] * ivB;  oB[1] = acc[e][3] * ivB;
            oB[8] = acc[e][6] * ivB;  oB[9] = acc[e][7] * ivB;
        }
    }
    if (t < NB * CAND && b0 + (t >> 4) < BATCH) {
        out[(size_t)(b0 * CAND + t) * OUTW + DIM + ADJW] = invs[t];  // ones column * inv
    }

    // ================= neighbor-mean phase (cols [0,256)) =================
    // (c, d4) pairs: 16 x 64 = 1024; rolling 7-of-13-slot window per pair.
    for (int p = t; p < CAND * (DIM / 4); p += FTHR) {
        const int c  = p & 15;
        const int d4 = p >> 4;          // 0..63

        auto loadE = [&](int s) -> float4 {
            const int bb = b0 - 3 + s;
            if ((unsigned)bb < BATCH)
                return *reinterpret_cast<const float4*>(
                    emb + ((size_t)bb * CAND + c) * DIM + d4 * 4);
            return make_float4(0.f, 0.f, 0.f, 0.f);
        };

        float4 w4[7];
        float  mm[6];
        #pragma unroll
        for (int i = 0; i < 7; i++) w4[i] = loadE(i);
        #pragma unroll
        for (int i = 0; i < 6; i++) mm[i] = nmv[i * CAND + c];

        #pragma unroll
        for (int bi2 = 0; bi2 < NB; bi2++) {
            const int b = b0 + bi2;
            const float L1 = mm[2], L2 = mm[2] * mm[1], L3 = mm[2] * mm[1] * mm[0];
            const float R1 = mm[3], R2 = mm[3] * mm[4], R3 = mm[3] * mm[4] * mm[5];
            if (b < BATCH) {
                float4 a4;
                a4.x = (w4[2].x*L1 + w4[1].x*L2 + w4[0].x*L3 + w4[4].x*R1 + w4[5].x*R2 + w4[6].x*R3) * (1.f/6.f);
                a4.y = (w4[2].y*L1 + w4[1].y*L2 + w4[0].y*L3 + w4[4].y*R1 + w4[5].y*R2 + w4[6].y*R3) * (1.f/6.f);
                a4.z = (w4[2].z*L1 + w4[1].z*L2 + w4[0].z*L3 + w4[4].z*R1 + w4[5].z*R2 + w4[6].z*R3) * (1.f/6.f);
                a4.w = (w4[2].w*L1 + w4[1].w*L2 + w4[0].w*L3 + w4[4].w*R1 + w4[5].w*R2 + w4[6].w*R3) * (1.f/6.f);
                float* o = out + (size_t)(b * CAND + c) * OUTW + d4 * 4;
                o[0] = a4.x; o[1] = a4.y; o[2] = a4.z; o[3] = a4.w;
            }
            if (bi2 < NB - 1) {
                #pragma unroll
                for (int i = 0; i < 6; i++) w4[i] = w4[i + 1];
                w4[6] = loadE(bi2 + 7);
                #pragma unroll
                for (int i = 0; i < 5; i++) mm[i] = mm[i + 1];
                mm[5] = nmv[(bi2 + 6) * CAND + c];
            }
        }
    }
}

// ---------------------------------------------------------------------------
extern "C" void kernel_launch(void* const* d_in, const int* in_sizes, int n_in,
                              void* d_out, int out_size) {
    (void)in_sizes; (void)n_in; (void)out_size;
    const float* emb = (const float*)d_in[0];
    const int*   nm  = (const int*)d_in[1];
    float*       out = (float*)d_out;

    (void)cudaFuncSetAttribute(k_all, cudaFuncAttributeMaxDynamicSharedMemorySize,
                               SMEM_TOTAL);

    k_all<<<FGRID, FTHR, SMEM_TOTAL>>>(emb, nm, out);
}

// round 14
// speedup vs baseline: 1.7624x; 1.7624x over previous
#include <cuda_runtime.h>
#include <cuda_bf16.h>
#include <cstdint>

#define BATCH 2048
#define CAND  16
#define DIM   256
#define ADJW  96                    // 2*3*16
#define OUTW  (DIM + ADJW + 1)      // 353
#define THRED 0.8f

// ---- fused kernel geometry (R8 base: best known 25.6us) ----
#define NB     7                    // batches per block
#define SLOTS  (NB + 6)             // 13 batch tiles incl. +-3 halo
#define BPAD   264                  // bf16 row stride (132 words == 4 mod 32: ldsm clean)
#define FTHR   448                  // threads (14 warps)
#define NROWST (SLOTS * CAND)       // 208 tile rows

#define OFF_TILES  0
#define SZ_TILES   (NROWST * BPAD * 2)                  // 109824 B
#define OFF_RSUM   (OFF_TILES + SZ_TILES)
#define SZ_RSUM    (NB * 6 * CAND * 4)                  // 2688 B
#define OFF_INVS   (OFF_RSUM + SZ_RSUM)
#define SZ_INVS    (NB * CAND * 4)                      // 448 B
#define OFF_INVN   (OFF_INVS + SZ_INVS)
#define SZ_INVN    (NROWST * 4)                         // 832 B
#define OFF_NMV    (OFF_INVN + SZ_INVN)
#define SZ_NMV     (NROWST * 4)                         // 832 B
#define SMEM_TOTAL (OFF_NMV + SZ_NMV)                   // 114624 B -> 2 CTAs/SM

#define FGRID ((BATCH + NB - 1) / NB)                   // 293 blocks ~ one wave

__device__ __forceinline__ uint32_t smem_u32(const void* p) {
    uint32_t a;
    asm("{ .reg .u64 t; cvta.to.shared.u64 t, %1; cvt.u32.u64 %0, t; }"
        : "=r"(a) : "l"(p));
    return a;
}

__device__ __forceinline__ void ldsm4(uint32_t addr, uint32_t& r0, uint32_t& r1,
                                      uint32_t& r2, uint32_t& r3) {
    asm volatile("ldmatrix.sync.aligned.m8n8.x4.shared.b16 {%0,%1,%2,%3}, [%4];"
                 : "=r"(r0), "=r"(r1), "=r"(r2), "=r"(r3) : "r"(addr));
}

__device__ __forceinline__ void mma16816(float* c, uint32_t a0, uint32_t a1,
                                         uint32_t a2, uint32_t a3,
                                         uint32_t b0, uint32_t b1) {
    asm volatile(
        "mma.sync.aligned.m16n8k16.row.col.f32.bf16.bf16.f32 "
        "{%0,%1,%2,%3}, {%4,%5,%6,%7}, {%8,%9}, {%0,%1,%2,%3};\n"
        : "+f"(c[0]), "+f"(c[1]), "+f"(c[2]), "+f"(c[3])
        : "r"(a0), "r"(a1), "r"(a2), "r"(a3), "r"(b0), "r"(b1));
}

// ---------------------------------------------------------------------------
// K_all: everything in one kernel.
//  cols [256,353): band cosine adjacency (R8 structure: bf16 tiles, ldmatrix,
//                  self-product MMA norms, threshold/gate/L1-normalize)
//  cols [0,256):   neighbor-mean, fp32 from emb (L2-hot re-read), rolling
//                  13-slot window; COALESCED mapping (d4 contiguous per warp).
// ---------------------------------------------------------------------------
__global__ __launch_bounds__(FTHR, 2) void k_all(const float* __restrict__ emb,
                                                 const int* __restrict__ nm,
                                                 float* __restrict__ out) {
    extern __shared__ __align__(16) char smraw[];
    __nv_bfloat16* tiles = reinterpret_cast<__nv_bfloat16*>(smraw + OFF_TILES); // [208][264]
    float* rsum = reinterpret_cast<float*>(smraw + OFF_RSUM);                   // [NB][6][16]
    float* invs = reinterpret_cast<float*>(smraw + OFF_INVS);                   // [NB][16]
    float* invn = reinterpret_cast<float*>(smraw + OFF_INVN);                   // [208]
    float* nmv  = reinterpret_cast<float*>(smraw + OFF_NMV);                    // [208]

    const int b0   = blockIdx.x * NB;
    const int t    = threadIdx.x;
    const int wid  = t >> 5;
    const int lane = t & 31;

    // ---- streaming copy+cast: 208 rows ----
    const int l8 = lane * 8;
    for (int r = wid; r < NROWST; r += FTHR / 32) {
        const int bb = b0 - 3 + (r >> 4);
        float4 v0 = make_float4(0.f, 0.f, 0.f, 0.f);
        float4 v1 = v0;
        if ((unsigned)bb < BATCH) {
            const float4* src = reinterpret_cast<const float4*>(
                emb + ((size_t)bb * CAND + (r & 15)) * DIM);
            v0 = src[lane * 2];
            v1 = src[lane * 2 + 1];
        }
        __nv_bfloat162 o[4];
        o[0] = __floats2bfloat162_rn(v0.x, v0.y);
        o[1] = __floats2bfloat162_rn(v0.z, v0.w);
        o[2] = __floats2bfloat162_rn(v1.x, v1.y);
        o[3] = __floats2bfloat162_rn(v1.z, v1.w);
        *reinterpret_cast<uint4*>(&tiles[(size_t)r * BPAD + l8]) = *reinterpret_cast<uint4*>(o);
    }

    // ---- mask cache: nmv[slot][j] (OOB batches -> 0) ----
    if (t < NROWST) {
        const int bb = b0 - 3 + (t >> 4);
        nmv[t] = ((unsigned)bb < BATCH) ? (float)nm[bb * CAND + (t & 15)] : 0.f;
    }
    __syncthreads();

    const int g  = lane >> 2;           // 0..7
    const int tg = lane & 3;            // 0..3
    const int jb = tg * 2;
    const int lmoff = (lane & 15) * BPAD + (lane >> 4) * 8;   // elements
    const uint32_t tiles_base = smem_u32(tiles);

    // ---- self-product MMAs: warps 0..12 compute invn for tile wid ----
    if (wid < SLOTS) {
        uint32_t sad = tiles_base + (uint32_t)(wid * CAND * BPAD + lmoff) * 2;
        float s0[4] = {0.f, 0.f, 0.f, 0.f};
        float s1[4] = {0.f, 0.f, 0.f, 0.f};
        #pragma unroll
        for (int kt = 0; kt < 16; kt++) {
            uint32_t a0, a1, a2, a3;
            ldsm4(sad, a0, a1, a2, a3);
            sad += 32;
            mma16816(s0, a0, a1, a2, a3, a0, a2);
            mma16816(s1, a0, a1, a2, a3, a1, a3);
        }
        if (tg == (g >> 1)) {
            invn[wid * CAND + g]     = rsqrtf(fmaxf((g & 1) ? s0[1] : s0[0], 1e-12f));
            invn[wid * CAND + g + 8] = rsqrtf(fmaxf((g & 1) ? s1[3] : s1[2], 1e-12f));
        }
    }

    // ---- pair MMAs: warp wid -> bi = wid/2, cps {0,1,2} or {3,4,5} ----
    const int bi = wid >> 1;            // 0..6
    const int cpb = (wid & 1) * 3;      // 0 (left) or 3 (right)
    const int slot = bi + 3;            // center tile slot

    uint32_t aad = tiles_base + (uint32_t)(slot * CAND * BPAD + lmoff) * 2;
    int bslot[3];
    uint32_t bad[3];
    #pragma unroll
    for (int e = 0; e < 3; e++) {
        bslot[e] = (cpb == 0) ? (slot - 1 - e) : (slot + 1 + e);
        bad[e] = tiles_base + (uint32_t)(bslot[e] * CAND * BPAD + lmoff) * 2;
    }

    float acc[3][8];
    #pragma unroll
    for (int e = 0; e < 3; e++)
        #pragma unroll
        for (int x = 0; x < 8; x++) acc[e][x] = 0.f;

    #pragma unroll
    for (int kt = 0; kt < 16; kt++) {
        uint32_t a0, a1, a2, a3;
        ldsm4(aad, a0, a1, a2, a3);
        aad += 32;
        #pragma unroll
        for (int e = 0; e < 3; e++) {
            uint32_t m0, m1, m2, m3;
            ldsm4(bad[e], m0, m1, m2, m3);
            bad[e] += 32;
            mma16816(acc[e],     a0, a1, a2, a3, m0, m2);
            mma16816(acc[e] + 4, a0, a1, a2, a3, m1, m3);
        }
    }
    __syncthreads();   // invn complete block-wide

    // ---- gates from mask cache ----
    float gj[4][3];
    const int js[4] = {jb, jb + 1, jb + 8, jb + 9};
    #pragma unroll
    for (int jx = 0; jx < 4; jx++) {
        float a, b, c;
        if (cpb == 0) {         // left: masks of batches b-1, b-2, b-3
            a = nmv[(slot - 1) * CAND + js[jx]];
            b = nmv[(slot - 2) * CAND + js[jx]];
            c = nmv[(slot - 3) * CAND + js[jx]];
        } else {                // right: masks of batches b, b+1, b+2
            a = nmv[slot * CAND + js[jx]];
            b = nmv[(slot + 1) * CAND + js[jx]];
            c = nmv[(slot + 2) * CAND + js[jx]];
        }
        gj[jx][0] = a;
        gj[jx][1] = a * b;
        gj[jx][2] = a * b * c;
    }

    // ---- epilogue: cosine scale, threshold, gate, partial row sums ----
    const float inA0 = invn[slot * CAND + g];
    const float inA8 = invn[slot * CAND + g + 8];
    #pragma unroll
    for (int e = 0; e < 3; e++) {
        const int cp = cpb + e;
        const float* np = &invn[bslot[e] * CAND];
        const float ib0 = np[jb], ib1 = np[jb + 1], ib8 = np[jb + 8], ib9 = np[jb + 9];
        auto thr = [](float v, float ge) {
            v = (v > THRED) ? fminf(v, 1.f) : 0.f;
            return v * ge;
        };
        acc[e][0] = thr(acc[e][0] * inA0 * ib0, gj[0][e]);
        acc[e][1] = thr(acc[e][1] * inA0 * ib1, gj[1][e]);
        acc[e][2] = thr(acc[e][2] * inA8 * ib0, gj[0][e]);
        acc[e][3] = thr(acc[e][3] * inA8 * ib1, gj[1][e]);
        acc[e][4] = thr(acc[e][4] * inA0 * ib8, gj[2][e]);
        acc[e][5] = thr(acc[e][5] * inA0 * ib9, gj[3][e]);
        acc[e][6] = thr(acc[e][6] * inA8 * ib8, gj[2][e]);
        acc[e][7] = thr(acc[e][7] * inA8 * ib9, gj[3][e]);

        float sA = acc[e][0] + acc[e][1] + acc[e][4] + acc[e][5]; // row g
        float sB = acc[e][2] + acc[e][3] + acc[e][6] + acc[e][7]; // row g+8
        sA += __shfl_xor_sync(0xffffffffu, sA, 1);
        sA += __shfl_xor_sync(0xffffffffu, sA, 2);
        sB += __shfl_xor_sync(0xffffffffu, sB, 1);
        sB += __shfl_xor_sync(0xffffffffu, sB, 2);
        if (tg == 0) {
            rsum[(bi * 6 + cp) * CAND + g]     = sA;
            rsum[(bi * 6 + cp) * CAND + g + 8] = sB;
        }
    }
    __syncthreads();

    // ---- invs: per output row 1 / (L1 sum + ones col) ----
    if (t < NB * CAND) {
        const int tb = t >> 4, i = t & 15;
        float s = 1.0f;
        #pragma unroll
        for (int cp = 0; cp < 6; cp++) s += rsum[(tb * 6 + cp) * CAND + i];
        invs[t] = 1.0f / fmaxf(s, 1e-12f);
    }
    __syncthreads();

    // ---- normalized adjacency writes (guard partial last block) ----
    if (b0 + bi < BATCH) {
        const float ivA = invs[bi * CAND + g];
        const float ivB = invs[bi * CAND + g + 8];
        #pragma unroll
        for (int e = 0; e < 3; e++) {
            const int cp = cpb + e;
            float* oA = out + (size_t)((b0 + bi) * CAND + g)     * OUTW + DIM + cp * CAND + jb;
            float* oB = out + (size_t)((b0 + bi) * CAND + g + 8) * OUTW + DIM + cp * CAND + jb;
            oA[0] = acc[e][0] * ivA;  oA[1] = acc[e][1] * ivA;
            oA[8] = acc[e][4] * ivA;  oA[9] = acc[e][5] * ivA;
            oB[0] = acc[e][2] * ivB;  oB[1] = acc[e][3] * ivB;
            oB[8] = acc[e][6] * ivB;  oB[9] = acc[e][7] * ivB;
        }
    }
    if (t < NB * CAND && b0 + (t >> 4) < BATCH) {
        out[(size_t)(b0 * CAND + t) * OUTW + DIM + ADJW] = invs[t];  // ones column * inv
    }

    // ================= neighbor-mean phase (cols [0,256)) =================
    // COALESCED: p -> c = p>>6 (same for a whole 64-thread group),
    // d4 = p&63 (contiguous) => warp sweeps one row's 1KB contiguously.
    for (int p = t; p < CAND * (DIM / 4); p += FTHR) {
        const int c  = p >> 6;          // 0..15
        const int d4 = p & 63;          // 0..63

        auto loadE = [&](int s) -> float4 {
            const int bb = b0 - 3 + s;
            if ((unsigned)bb < BATCH)
                return *reinterpret_cast<const float4*>(
                    emb + ((size_t)bb * CAND + c) * DIM + d4 * 4);
            return make_float4(0.f, 0.f, 0.f, 0.f);
        };

        float4 w4[7];
        float  mm[6];
        #pragma unroll
        for (int i = 0; i < 7; i++) w4[i] = loadE(i);
        #pragma unroll
        for (int i = 0; i < 6; i++) mm[i] = nmv[i * CAND + c];

        #pragma unroll
        for (int bi2 = 0; bi2 < NB; bi2++) {
            const int b = b0 + bi2;
            const float L1 = mm[2], L2 = mm[2] * mm[1], L3 = mm[2] * mm[1] * mm[0];
            const float R1 = mm[3], R2 = mm[3] * mm[4], R3 = mm[3] * mm[4] * mm[5];
            if (b < BATCH) {
                float4 a4;
                a4.x = (w4[2].x*L1 + w4[1].x*L2 + w4[0].x*L3 + w4[4].x*R1 + w4[5].x*R2 + w4[6].x*R3) * (1.f/6.f);
                a4.y = (w4[2].y*L1 + w4[1].y*L2 + w4[0].y*L3 + w4[4].y*R1 + w4[5].y*R2 + w4[6].y*R3) * (1.f/6.f);
                a4.z = (w4[2].z*L1 + w4[1].z*L2 + w4[0].z*L3 + w4[4].z*R1 + w4[5].z*R2 + w4[6].z*R3) * (1.f/6.f);
                a4.w = (w4[2].w*L1 + w4[1].w*L2 + w4[0].w*L3 + w4[4].w*R1 + w4[5].w*R2 + w4[6].w*R3) * (1.f/6.f);
                float* o = out + (size_t)(b * CAND + c) * OUTW + d4 * 4;
                o[0] = a4.x; o[1] = a4.y; o[2] = a4.z; o[3] = a4.w;
            }
            if (bi2 < NB - 1) {
                #pragma unroll
                for (int i = 0; i < 6; i++) w4[i] = w4[i + 1];
                w4[6] = loadE(bi2 + 7);
                #pragma unroll
                for (int i = 0; i < 5; i++) mm[i] = mm[i + 1];
                mm[5] = nmv[(bi2 + 6) * CAND + c];
            }
        }
    }
}

// ---------------------------------------------------------------------------
extern "C" void kernel_launch(void* const* d_in, const int* in_sizes, int n_in,
                              void* d_out, int out_size) {
    (void)in_sizes; (void)n_in; (void)out_size;
    const float* emb = (const float*)d_in[0];
    const int*   nm  = (const int*)d_in[1];
    float*       out = (float*)d_out;

    (void)cudaFuncSetAttribute(k_all, cudaFuncAttributeMaxDynamicSharedMemorySize,
                               SMEM_TOTAL);

    k_all<<<FGRID, FTHR, SMEM_TOTAL>>>(emb, nm, out);
}

// round 15
// speedup vs baseline: 1.8383x; 1.0431x over previous
#include <cuda_runtime.h>
#include <cuda_bf16.h>
#include <cstdint>

#define BATCH 2048
#define CAND  16
#define DIM   256
#define ADJW  96                    // 2*3*16
#define OUTW  (DIM + ADJW + 1)      // 353
#define THRED 0.8f

// ---- fused kernel geometry ----
#define NB     7                    // batches per block
#define SLOTS  (NB + 6)             // 13 batch tiles incl. +-3 halo
#define BPAD   264                  // bf16 row stride (132 words == 4 mod 32: ldsm clean)
#define FTHR   448                  // threads (14 warps)
#define NROWST (SLOTS * CAND)       // 208 tile rows

#define OFF_TILES  0
#define SZ_TILES   (NROWST * BPAD * 2)                  // 109824 B
#define OFF_RSUM   (OFF_TILES + SZ_TILES)
#define SZ_RSUM    (NB * 6 * CAND * 4)                  // 2688 B
#define OFF_INVS   (OFF_RSUM + SZ_RSUM)
#define SZ_INVS    (NB * CAND * 4)                      // 448 B
#define OFF_INVN   (OFF_INVS + SZ_INVS)
#define SZ_INVN    (NROWST * 4)                         // 832 B
#define OFF_NMV    (OFF_INVN + SZ_INVN)
#define SZ_NMV     (NROWST * 4)                         // 832 B
#define SMEM_TOTAL (OFF_NMV + SZ_NMV)                   // 114624 B -> 2 CTAs/SM

#define FGRID ((BATCH + NB - 1) / NB)                   // 293 blocks ~ one wave

__device__ __forceinline__ uint32_t smem_u32(const void* p) {
    uint32_t a;
    asm("{ .reg .u64 t; cvta.to.shared.u64 t, %1; cvt.u32.u64 %0, t; }"
        : "=r"(a) : "l"(p));
    return a;
}

__device__ __forceinline__ void ldsm4(uint32_t addr, uint32_t& r0, uint32_t& r1,
                                      uint32_t& r2, uint32_t& r3) {
    asm volatile("ldmatrix.sync.aligned.m8n8.x4.shared.b16 {%0,%1,%2,%3}, [%4];"
                 : "=r"(r0), "=r"(r1), "=r"(r2), "=r"(r3) : "r"(addr));
}

__device__ __forceinline__ void mma16816(float* c, uint32_t a0, uint32_t a1,
                                         uint32_t a2, uint32_t a3,
                                         uint32_t b0, uint32_t b1) {
    asm volatile(
        "mma.sync.aligned.m16n8k16.row.col.f32.bf16.bf16.f32 "
        "{%0,%1,%2,%3}, {%4,%5,%6,%7}, {%8,%9}, {%0,%1,%2,%3};\n"
        : "+f"(c[0]), "+f"(c[1]), "+f"(c[2]), "+f"(c[3])
        : "r"(a0), "r"(a1), "r"(a2), "r"(a3), "r"(b0), "r"(b1));
}

// ---------------------------------------------------------------------------
// K_all: everything in one kernel.
//  cols [256,353): band cosine adjacency (bf16 tiles, ldmatrix, self-product
//                  MMA norms, threshold/gate/L1-normalize)
//  cols [0,256):   neighbor-mean, fp32 from emb (L2-hot), coalesced, with
//                  ALL 13 window loads issued upfront (MLP=13, no rolling).
// ---------------------------------------------------------------------------
__global__ __launch_bounds__(FTHR, 2) void k_all(const float* __restrict__ emb,
                                                 const int* __restrict__ nm,
                                                 float* __restrict__ out) {
    extern __shared__ __align__(16) char smraw[];
    __nv_bfloat16* tiles = reinterpret_cast<__nv_bfloat16*>(smraw + OFF_TILES); // [208][264]
    float* rsum = reinterpret_cast<float*>(smraw + OFF_RSUM);                   // [NB][6][16]
    float* invs = reinterpret_cast<float*>(smraw + OFF_INVS);                   // [NB][16]
    float* invn = reinterpret_cast<float*>(smraw + OFF_INVN);                   // [208]
    float* nmv  = reinterpret_cast<float*>(smraw + OFF_NMV);                    // [208]

    const int b0   = blockIdx.x * NB;
    const int t    = threadIdx.x;
    const int wid  = t >> 5;
    const int lane = t & 31;

    // ---- streaming copy+cast: 208 rows ----
    const int l8 = lane * 8;
    for (int r = wid; r < NROWST; r += FTHR / 32) {
        const int bb = b0 - 3 + (r >> 4);
        float4 v0 = make_float4(0.f, 0.f, 0.f, 0.f);
        float4 v1 = v0;
        if ((unsigned)bb < BATCH) {
            const float4* src = reinterpret_cast<const float4*>(
                emb + ((size_t)bb * CAND + (r & 15)) * DIM);
            v0 = src[lane * 2];
            v1 = src[lane * 2 + 1];
        }
        __nv_bfloat162 o[4];
        o[0] = __floats2bfloat162_rn(v0.x, v0.y);
        o[1] = __floats2bfloat162_rn(v0.z, v0.w);
        o[2] = __floats2bfloat162_rn(v1.x, v1.y);
        o[3] = __floats2bfloat162_rn(v1.z, v1.w);
        *reinterpret_cast<uint4*>(&tiles[(size_t)r * BPAD + l8]) = *reinterpret_cast<uint4*>(o);
    }

    // ---- mask cache: nmv[slot][j] (OOB batches -> 0) ----
    if (t < NROWST) {
        const int bb = b0 - 3 + (t >> 4);
        nmv[t] = ((unsigned)bb < BATCH) ? (float)nm[bb * CAND + (t & 15)] : 0.f;
    }
    __syncthreads();

    const int g  = lane >> 2;           // 0..7
    const int tg = lane & 3;            // 0..3
    const int jb = tg * 2;
    const int lmoff = (lane & 15) * BPAD + (lane >> 4) * 8;   // elements
    const uint32_t tiles_base = smem_u32(tiles);

    // ---- self-product MMAs: warps 0..12 compute invn for tile wid ----
    if (wid < SLOTS) {
        uint32_t sad = tiles_base + (uint32_t)(wid * CAND * BPAD + lmoff) * 2;
        float s0[4] = {0.f, 0.f, 0.f, 0.f};
        float s1[4] = {0.f, 0.f, 0.f, 0.f};
        #pragma unroll
        for (int kt = 0; kt < 16; kt++) {
            uint32_t a0, a1, a2, a3;
            ldsm4(sad, a0, a1, a2, a3);
            sad += 32;
            mma16816(s0, a0, a1, a2, a3, a0, a2);
            mma16816(s1, a0, a1, a2, a3, a1, a3);
        }
        if (tg == (g >> 1)) {
            invn[wid * CAND + g]     = rsqrtf(fmaxf((g & 1) ? s0[1] : s0[0], 1e-12f));
            invn[wid * CAND + g + 8] = rsqrtf(fmaxf((g & 1) ? s1[3] : s1[2], 1e-12f));
        }
    }

    // ---- pair MMAs: warp wid -> bi = wid/2, cps {0,1,2} or {3,4,5} ----
    const int bi = wid >> 1;            // 0..6
    const int cpb = (wid & 1) * 3;      // 0 (left) or 3 (right)
    const int slot = bi + 3;            // center tile slot

    uint32_t aad = tiles_base + (uint32_t)(slot * CAND * BPAD + lmoff) * 2;
    int bslot[3];
    uint32_t bad[3];
    #pragma unroll
    for (int e = 0; e < 3; e++) {
        bslot[e] = (cpb == 0) ? (slot - 1 - e) : (slot + 1 + e);
        bad[e] = tiles_base + (uint32_t)(bslot[e] * CAND * BPAD + lmoff) * 2;
    }

    float acc[3][8];
    #pragma unroll
    for (int e = 0; e < 3; e++)
        #pragma unroll
        for (int x = 0; x < 8; x++) acc[e][x] = 0.f;

    #pragma unroll
    for (int kt = 0; kt < 16; kt++) {
        uint32_t a0, a1, a2, a3;
        ldsm4(aad, a0, a1, a2, a3);
        aad += 32;
        #pragma unroll
        for (int e = 0; e < 3; e++) {
            uint32_t m0, m1, m2, m3;
            ldsm4(bad[e], m0, m1, m2, m3);
            bad[e] += 32;
            mma16816(acc[e],     a0, a1, a2, a3, m0, m2);
            mma16816(acc[e] + 4, a0, a1, a2, a3, m1, m3);
        }
    }
    __syncthreads();   // invn complete block-wide

    // ---- gates from mask cache ----
    float gj[4][3];
    const int js[4] = {jb, jb + 1, jb + 8, jb + 9};
    #pragma unroll
    for (int jx = 0; jx < 4; jx++) {
        float a, b, c;
        if (cpb == 0) {         // left: masks of batches b-1, b-2, b-3
            a = nmv[(slot - 1) * CAND + js[jx]];
            b = nmv[(slot - 2) * CAND + js[jx]];
            c = nmv[(slot - 3) * CAND + js[jx]];
        } else {                // right: masks of batches b, b+1, b+2
            a = nmv[slot * CAND + js[jx]];
            b = nmv[(slot + 1) * CAND + js[jx]];
            c = nmv[(slot + 2) * CAND + js[jx]];
        }
        gj[jx][0] = a;
        gj[jx][1] = a * b;
        gj[jx][2] = a * b * c;
    }

    // ---- epilogue: cosine scale, threshold, gate, partial row sums ----
    const float inA0 = invn[slot * CAND + g];
    const float inA8 = invn[slot * CAND + g + 8];
    #pragma unroll
    for (int e = 0; e < 3; e++) {
        const int cp = cpb + e;
        const float* np = &invn[bslot[e] * CAND];
        const float ib0 = np[jb], ib1 = np[jb + 1], ib8 = np[jb + 8], ib9 = np[jb + 9];
        auto thr = [](float v, float ge) {
            v = (v > THRED) ? fminf(v, 1.f) : 0.f;
            return v * ge;
        };
        acc[e][0] = thr(acc[e][0] * inA0 * ib0, gj[0][e]);
        acc[e][1] = thr(acc[e][1] * inA0 * ib1, gj[1][e]);
        acc[e][2] = thr(acc[e][2] * inA8 * ib0, gj[0][e]);
        acc[e][3] = thr(acc[e][3] * inA8 * ib1, gj[1][e]);
        acc[e][4] = thr(acc[e][4] * inA0 * ib8, gj[2][e]);
        acc[e][5] = thr(acc[e][5] * inA0 * ib9, gj[3][e]);
        acc[e][6] = thr(acc[e][6] * inA8 * ib8, gj[2][e]);
        acc[e][7] = thr(acc[e][7] * inA8 * ib9, gj[3][e]);

        float sA = acc[e][0] + acc[e][1] + acc[e][4] + acc[e][5]; // row g
        float sB = acc[e][2] + acc[e][3] + acc[e][6] + acc[e][7]; // row g+8
        sA += __shfl_xor_sync(0xffffffffu, sA, 1);
        sA += __shfl_xor_sync(0xffffffffu, sA, 2);
        sB += __shfl_xor_sync(0xffffffffu, sB, 1);
        sB += __shfl_xor_sync(0xffffffffu, sB, 2);
        if (tg == 0) {
            rsum[(bi * 6 + cp) * CAND + g]     = sA;
            rsum[(bi * 6 + cp) * CAND + g + 8] = sB;
        }
    }
    __syncthreads();

    // ---- invs: per output row 1 / (L1 sum + ones col) ----
    if (t < NB * CAND) {
        const int tb = t >> 4, i = t & 15;
        float s = 1.0f;
        #pragma unroll
        for (int cp = 0; cp < 6; cp++) s += rsum[(tb * 6 + cp) * CAND + i];
        invs[t] = 1.0f / fmaxf(s, 1e-12f);
    }
    __syncthreads();

    // ---- normalized adjacency writes (guard partial last block) ----
    if (b0 + bi < BATCH) {
        const float ivA = invs[bi * CAND + g];
        const float ivB = invs[bi * CAND + g + 8];
        #pragma unroll
        for (int e = 0; e < 3; e++) {
            const int cp = cpb + e;
            float* oA = out + (size_t)((b0 + bi) * CAND + g)     * OUTW + DIM + cp * CAND + jb;
            float* oB = out + (size_t)((b0 + bi) * CAND + g + 8) * OUTW + DIM + cp * CAND + jb;
            oA[0] = acc[e][0] * ivA;  oA[1] = acc[e][1] * ivA;
            oA[8] = acc[e][4] * ivA;  oA[9] = acc[e][5] * ivA;
            oB[0] = acc[e][2] * ivB;  oB[1] = acc[e][3] * ivB;
            oB[8] = acc[e][6] * ivB;  oB[9] = acc[e][7] * ivB;
        }
    }
    if (t < NB * CAND && b0 + (t >> 4) < BATCH) {
        out[(size_t)(b0 * CAND + t) * OUTW + DIM + ADJW] = invs[t];  // ones column * inv
    }

    // ================= neighbor-mean phase (cols [0,256)) =================
    // COALESCED (c = p>>6 shared per 64-thread group, d4 = p&63 contiguous).
    // ALL 13 window loads issued upfront (MLP=13), outputs by static indexing.
    for (int p = t; p < CAND * (DIM / 4); p += FTHR) {
        const int c  = p >> 6;          // 0..15
        const int d4 = p & 63;          // 0..63

        float4 w4[SLOTS];
        #pragma unroll
        for (int s = 0; s < SLOTS; s++) {
            const int bb = b0 - 3 + s;
            float4 x = make_float4(0.f, 0.f, 0.f, 0.f);
            if ((unsigned)bb < BATCH)
                x = *reinterpret_cast<const float4*>(
                    emb + ((size_t)bb * CAND + c) * DIM + d4 * 4);
            w4[s] = x;
        }
        float mmv[SLOTS];
        #pragma unroll
        for (int s = 0; s < SLOTS; s++) mmv[s] = nmv[s * CAND + c];

        #pragma unroll
        for (int bi2 = 0; bi2 < NB; bi2++) {
            const int b = b0 + bi2;
            if (b >= BATCH) continue;
            // window for batch b: slots bi2..bi2+6, center at bi2+3
            const float L1 = mmv[bi2 + 2];
            const float L2 = L1 * mmv[bi2 + 1];
            const float L3 = L2 * mmv[bi2];
            const float R1 = mmv[bi2 + 3];
            const float R2 = R1 * mmv[bi2 + 4];
            const float R3 = R2 * mmv[bi2 + 5];
            const float4 wl1 = w4[bi2 + 2], wl2 = w4[bi2 + 1], wl3 = w4[bi2];
            const float4 wr1 = w4[bi2 + 4], wr2 = w4[bi2 + 5], wr3 = w4[bi2 + 6];
            float4 a4;
            a4.x = (wl1.x*L1 + wl2.x*L2 + wl3.x*L3 + wr1.x*R1 + wr2.x*R2 + wr3.x*R3) * (1.f/6.f);
            a4.y = (wl1.y*L1 + wl2.y*L2 + wl3.y*L3 + wr1.y*R1 + wr2.y*R2 + wr3.y*R3) * (1.f/6.f);
            a4.z = (wl1.z*L1 + wl2.z*L2 + wl3.z*L3 + wr1.z*R1 + wr2.z*R2 + wr3.z*R3) * (1.f/6.f);
            a4.w = (wl1.w*L1 + wl2.w*L2 + wl3.w*L3 + wr1.w*R1 + wr2.w*R2 + wr3.w*R3) * (1.f/6.f);
            float* o = out + (size_t)(b * CAND + c) * OUTW + d4 * 4;
            o[0] = a4.x; o[1] = a4.y; o[2] = a4.z; o[3] = a4.w;
        }
    }
}

// ---------------------------------------------------------------------------
extern "C" void kernel_launch(void* const* d_in, const int* in_sizes, int n_in,
                              void* d_out, int out_size) {
    (void)in_sizes; (void)n_in; (void)out_size;
    const float* emb = (const float*)d_in[0];
    const int*   nm  = (const int*)d_in[1];
    float*       out = (float*)d_out;

    (void)cudaFuncSetAttribute(k_all, cudaFuncAttributeMaxDynamicSharedMemorySize,
                               SMEM_TOTAL);

    k_all<<<FGRID, FTHR, SMEM_TOTAL>>>(emb, nm, out);
}